// round 5
// baseline (speedup 1.0000x reference)
#include <cuda_runtime.h>
#include <math.h>

// out = -mean_b log(y[b, argmax(target_b)] + 1e-8)
//       + sum_{b,c} wtab[popc(t_b ^ c)] * y[b,c] / (B*N)
// N = 1024 (10 bits), wtab[0]=0, wtab[p]=6^p (exact in fp32).

#define NCLS   1024
#define SMS    152
#define CPS    2          // 2 CTAs/SM: room for the pipelined register set
#define BLOCKS (SMS * CPS)
#define TPB    256
#define WPB    (TPB / 32)

__device__ double   g_ce = 0.0;
__device__ double   g_pt = 0.0;
__device__ unsigned g_count = 0;

__global__ __launch_bounds__(TPB, CPS)
void ce_pt_kernel(const float* __restrict__ y, const float* __restrict__ tgt,
                  float* __restrict__ out, int B) {
    __shared__ float  wtab[16];
    __shared__ double s_ce[WPB], s_pt[WPB];

    const int tid  = threadIdx.x;
    const int lane = tid & 31;
    const int wid  = tid >> 5;

    if (tid < 11) {
        float w = 1.0f;
        for (int i = 0; i < tid; i++) w *= 6.0f;   // exact: 6^10 < 2^26
        wtab[tid] = (tid == 0) ? 0.0f : w;
    }
    __syncthreads();

    const int gw = blockIdx.x * WPB + wid;
    const int nw = gridDim.x * WPB;

    float  acc_pt = 0.0f;
    double acc_ce = 0.0;

    float4 tv[8], yv[8];

    // ---- prologue: load first row (every warp has >= 1 row: nw <= B) ----
    {
        const float4* trow = (const float4*)(tgt + (size_t)gw * NCLS);
        const float4* yrow = (const float4*)(y   + (size_t)gw * NCLS);
        #pragma unroll
        for (int it = 0; it < 8; it++) {
            tv[it] = __ldcs(&trow[it * 32 + lane]);
            yv[it] = __ldcs(&yrow[it * 32 + lane]);
        }
    }

    for (int r = gw; r < B; r += nw) {
        const int  rn       = r + nw;
        const bool has_next = rn < B;                 // warp-uniform
        const float4* trowN = (const float4*)(tgt + (size_t)(has_next ? rn : r) * NCLS);
        const float4* yrowN = (const float4*)(y   + (size_t)(has_next ? rn : r) * NCLS);

        // ---- argmax scan over tv: packed u64 key (fbits<<32)|(N-1-idx) ----
        // positive uniforms -> IEEE bits monotonic; complemented idx = first-max ties.
        unsigned long long bk = 0ull;
        #pragma unroll
        for (int it = 0; it < 8; it++) {
            int c = (it * 32 + lane) * 4;
            unsigned long long k;
            k = ((unsigned long long)__float_as_uint(tv[it].x) << 32) | (unsigned)(NCLS - 1 - c);
            if (k > bk) bk = k;
            k = ((unsigned long long)__float_as_uint(tv[it].y) << 32) | (unsigned)(NCLS - 2 - c);
            if (k > bk) bk = k;
            k = ((unsigned long long)__float_as_uint(tv[it].z) << 32) | (unsigned)(NCLS - 3 - c);
            if (k > bk) bk = k;
            k = ((unsigned long long)__float_as_uint(tv[it].w) << 32) | (unsigned)(NCLS - 4 - c);
            if (k > bk) bk = k;
        }

        // ---- tv is dead: prefetch next row's target NOW (flies during reduce) ----
        if (has_next) {
            #pragma unroll
            for (int it = 0; it < 8; it++)
                tv[it] = __ldcs(&trowN[it * 32 + lane]);
        }

        // ---- shuffle reduce bk -> t ----
        #pragma unroll
        for (int off = 16; off; off >>= 1) {
            unsigned long long ok = __shfl_xor_sync(0xFFFFFFFFu, bk, off);
            if (ok > bk) bk = ok;
        }
        const int t = NCLS - 1 - (int)(bk & 0xFFFFFFFFu);

        // ---- CE term: extract y[t] before yv gets overwritten ----
        if (lane == ((t >> 2) & 31)) {
            const int itq = t >> 7;
            const int cq  = t & 3;
            float4 v = yv[0];
            #pragma unroll
            for (int it = 1; it < 8; it++) if (it == itq) v = yv[it];
            float yt = (cq == 0) ? v.x : (cq == 1) ? v.y : (cq == 2) ? v.z : v.w;
            acc_ce += (double)logf(yt + 1e-8f);
        }

        // ---- weighted sum (factored popcount, 4 accumulators); reload yv as consumed ----
        const int tb = t >> 2;
        const int tl = t & 3;
        const int d0 = __popc(tl ^ 0), d1 = __popc(tl ^ 1);
        const int d2 = __popc(tl ^ 2), d3 = __popc(tl ^ 3);

        float p0 = 0.0f, p1 = 0.0f, p2 = 0.0f, p3 = 0.0f;
        #pragma unroll
        for (int it = 0; it < 8; it++) {
            const int cb = it * 32 + lane;
            const int pb = __popc(tb ^ cb);
            p0 = fmaf(wtab[pb + d0], yv[it].x, p0);
            p1 = fmaf(wtab[pb + d1], yv[it].y, p1);
            p2 = fmaf(wtab[pb + d2], yv[it].z, p2);
            p3 = fmaf(wtab[pb + d3], yv[it].w, p3);
            if (has_next) yv[it] = __ldcs(&yrowN[it * 32 + lane]);   // prefetch next row
        }
        acc_pt += (p0 + p1) + (p2 + p3);
    }

    // ---- warp reduce (once) ----
    double dpt = (double)acc_pt;
    #pragma unroll
    for (int off = 16; off; off >>= 1) {
        dpt    += __shfl_xor_sync(0xFFFFFFFFu, dpt,    off);
        acc_ce += __shfl_xor_sync(0xFFFFFFFFu, acc_ce, off);
    }
    if (lane == 0) { s_ce[wid] = acc_ce; s_pt[wid] = dpt; }
    __syncthreads();

    // ---- block reduce + fenced last-block finish ----
    if (tid == 0) {
        double bce = 0.0, bpt = 0.0;
        #pragma unroll
        for (int i = 0; i < WPB; i++) { bce += s_ce[i]; bpt += s_pt[i]; }
        atomicAdd(&g_ce, bce);
        atomicAdd(&g_pt, bpt);
        __threadfence();
        unsigned old = atomicAdd(&g_count, 1u);
        if (old == gridDim.x - 1) {
            double CE = atomicAdd(&g_ce, 0.0);   // L2 read (bypass stale L1)
            double PT = atomicAdd(&g_pt, 0.0);
            out[0] = (float)(-CE / (double)B + PT / ((double)B * (double)NCLS));
            g_ce = 0.0;                           // reset for next graph replay
            g_pt = 0.0;
            g_count = 0u;
        }
    }
}

extern "C" void kernel_launch(void* const* d_in, const int* in_sizes, int n_in,
                              void* d_out, int out_size) {
    const float* y_true = (const float*)d_in[0];
    const float* target = (const float*)d_in[1];
    const int B = in_sizes[0] / NCLS;

    ce_pt_kernel<<<BLOCKS, TPB>>>(y_true, target, (float*)d_out, B);
}